// round 17
// baseline (speedup 1.0000x reference)
#include <cuda_runtime.h>
#include <cuda_fp16.h>
#include <math.h>
#include <stdint.h>

#define NNODES 100000
#define NEDGES 3200000
#define NF 256
#define NCHUNK 4
#define CHUNK_ROWS 25088   // 196 * 128

// ---------------- scratch (device globals; no allocs allowed) ----------------
__device__ __half g_h0[(size_t)NNODES * NF];
__device__ __half g_h1[(size_t)NNODES * NF];
__device__ __half g_h2[(size_t)NNODES * NF];
__device__ int   g_rowptr[NNODES + 1];
__device__ int   g_cursor[NNODES];
__device__ uint2 g_cw[NEDGES];
__device__ __half g_Wh[3][NF * NF];
__device__ __half g_W4p[64 * NF];

// ---------------- helpers ----------------
__device__ __forceinline__ uint32_t smem_u32(const void* p) {
    uint32_t a;
    asm("{ .reg .u64 t; cvta.to.shared.u64 t, %1; cvt.u32.u64 %0, t; }" : "=r"(a) : "l"(p));
    return a;
}

#define LDSM_X4(r0, r1, r2, r3, addr) \
    asm volatile("ldmatrix.sync.aligned.m8n8.x4.shared.b16 {%0,%1,%2,%3}, [%4];" \
                 : "=r"(r0), "=r"(r1), "=r"(r2), "=r"(r3) : "r"(addr))

__device__ __forceinline__ void mma_f16(float* d, const uint32_t* a, const uint32_t* b) {
    asm volatile(
        "mma.sync.aligned.m16n8k16.row.col.f32.f16.f16.f32 "
        "{%0,%1,%2,%3}, {%4,%5,%6,%7}, {%8,%9}, {%0,%1,%2,%3};"
        : "+f"(d[0]), "+f"(d[1]), "+f"(d[2]), "+f"(d[3])
        : "r"(a[0]), "r"(a[1]), "r"(a[2]), "r"(a[3]), "r"(b[0]), "r"(b[1]));
}

#define CP_ASYNC16(dst, src) \
    asm volatile("cp.async.cg.shared.global [%0], [%1], 16;" :: "r"(dst), "l"(src))
#define CP_COMMIT() asm volatile("cp.async.commit_group;")
#define CP_WAIT1() asm volatile("cp.async.wait_group 1;")
#define CP_WAIT0() asm volatile("cp.async.wait_group 0;")

__device__ __forceinline__ uint64_t pack_f32x2(float lo, float hi) {
    uint64_t r;
    asm("mov.b64 %0, {%1, %2};" : "=l"(r) : "f"(lo), "f"(hi));
    return r;
}
__device__ __forceinline__ void unpack_f32x2(uint64_t v, float& lo, float& hi) {
    asm("mov.b64 {%0, %1}, %2;" : "=f"(lo), "=f"(hi) : "l"(v));
}
__device__ __forceinline__ void fma_f32x2(uint64_t& acc, uint64_t a, uint64_t b) {
    asm("fma.rn.f32x2 %0, %1, %2, %0;" : "+l"(acc) : "l"(a), "l"(b));
}

// ---------------- merged: x -> fp16 copy + degree histogram ----------------
__global__ void conv_hist_kernel(const float* __restrict__ x, __half* __restrict__ xh,
                                 const int* __restrict__ erow, int E, int total4) {
    int i = (blockIdx.x * blockDim.x + threadIdx.x) * 2;
#pragma unroll
    for (int j = 0; j < 2; j++) {
        int k = i + j;
        if (k < total4) {
            float4 v = ((const float4*)x)[k];
            __half h[4] = {__float2half_rn(v.x), __float2half_rn(v.y),
                           __float2half_rn(v.z), __float2half_rn(v.w)};
            *(uint2*)(xh + (size_t)k * 4) = *(uint2*)h;
        }
        if (k < E) atomicAdd(&g_rowptr[erow[k]], 1);
    }
}

__global__ void scan_kernel(int n) {
    __shared__ int part[1024];
    int t = threadIdx.x;
    int CH = (n + 1023) / 1024;
    int beg = t * CH;
    int end = min(beg + CH, n);
    int s = 0;
    for (int i = beg; i < end; i++) s += g_rowptr[i];
    part[t] = s;
    __syncthreads();
    for (int off = 1; off < 1024; off <<= 1) {
        int v = (t >= off) ? part[t - off] : 0;
        __syncthreads();
        part[t] += v;
        __syncthreads();
    }
    int base = (t == 0) ? 0 : part[t - 1];
    int run = base;
    for (int i = beg; i < end; i++) {
        int c = g_rowptr[i];
        g_rowptr[i] = run;
        g_cursor[i] = run;
        run += c;
    }
    if (t == 1023) g_rowptr[n] = part[1023];
}

__global__ void scatter_kernel(const int* __restrict__ erow,
                               const int* __restrict__ ecol,
                               const float* __restrict__ ew, int E) {
    int i = (blockIdx.x * blockDim.x + threadIdx.x) * 4;
#pragma unroll
    for (int j = 0; j < 4; j++) {
        if (i + j < E) {
            int r = erow[i + j];
            int pos = atomicAdd(&g_cursor[r], 1);
            uint2 cw;
            cw.x = (uint32_t)ecol[i + j] * 512u;
            cw.y = __float_as_uint(ew[i + j]);
            g_cw[pos] = cw;
        }
    }
}

// ---------------- SPMM: one warp per row, row range [row0, rowEnd) ----------------
__global__ void __launch_bounds__(256, 6) spmm_f16_kernel(
    const __half* __restrict__ src, __half* __restrict__ dst, int row0, int rowEnd) {
    int row = row0 + ((blockIdx.x * blockDim.x + threadIdx.x) >> 5);
    if (row >= rowEnd) return;
    int lane = threadIdx.x & 31;
    uint32_t foff = (uint32_t)lane * 16;
    const char* sp = (const char*)src;

    uint4 rv = __ldg((const uint4*)(sp + (size_t)row * 512 + foff));
    float2 q0 = __half22float2(*(__half2*)&rv.x);
    float2 q1 = __half22float2(*(__half2*)&rv.y);
    float2 q2 = __half22float2(*(__half2*)&rv.z);
    float2 q3 = __half22float2(*(__half2*)&rv.w);
    uint64_t A0 = pack_f32x2(q0.x, q0.y);
    uint64_t A1 = pack_f32x2(q1.x, q1.y);
    uint64_t A2 = pack_f32x2(q2.x, q2.y);
    uint64_t A3 = pack_f32x2(q3.x, q3.y);

    int beg = g_rowptr[row], end = g_rowptr[row + 1];
    int e = beg;

    auto acc1 = [&](uint32_t coff, uint32_t wbits) {
        float w = __uint_as_float(wbits);
        uint64_t w2 = pack_f32x2(w, w);
        uint4 v = __ldg((const uint4*)(sp + (size_t)(coff + foff)));
        float2 p0 = __half22float2(*(__half2*)&v.x);
        float2 p1 = __half22float2(*(__half2*)&v.y);
        float2 p2 = __half22float2(*(__half2*)&v.z);
        float2 p3 = __half22float2(*(__half2*)&v.w);
        fma_f32x2(A0, pack_f32x2(p0.x, p0.y), w2);
        fma_f32x2(A1, pack_f32x2(p1.x, p1.y), w2);
        fma_f32x2(A2, pack_f32x2(p2.x, p2.y), w2);
        fma_f32x2(A3, pack_f32x2(p3.x, p3.y), w2);
    };

    if ((e & 1) && e < end) {
        uint2 cw = __ldg(&g_cw[e]);
        acc1(cw.x, cw.y);
        e++;
    }
    const uint4* cw4 = (const uint4*)g_cw;
    for (; e + 8 <= end; e += 8) {
        uint4 c0 = __ldg(&cw4[(e >> 1) + 0]);
        uint4 c1 = __ldg(&cw4[(e >> 1) + 1]);
        uint4 c2 = __ldg(&cw4[(e >> 1) + 2]);
        uint4 c3 = __ldg(&cw4[(e >> 1) + 3]);
        acc1(c0.x, c0.y); acc1(c0.z, c0.w);
        acc1(c1.x, c1.y); acc1(c1.z, c1.w);
        acc1(c2.x, c2.y); acc1(c2.z, c2.w);
        acc1(c3.x, c3.y); acc1(c3.z, c3.w);
    }
    for (; e + 2 <= end; e += 2) {
        uint4 c = __ldg(&cw4[e >> 1]);
        acc1(c.x, c.y); acc1(c.z, c.w);
    }
    if (e < end) {
        uint2 cw = __ldg(&g_cw[e]);
        acc1(cw.x, cw.y);
    }

    float a0, a1, a2, a3, a4, a5, a6, a7;
    unpack_f32x2(A0, a0, a1);
    unpack_f32x2(A1, a2, a3);
    unpack_f32x2(A2, a4, a5);
    unpack_f32x2(A3, a6, a7);
    __half o[8] = {__float2half_rn(a0), __float2half_rn(a1),
                   __float2half_rn(a2), __float2half_rn(a3),
                   __float2half_rn(a4), __float2half_rn(a5),
                   __float2half_rn(a6), __float2half_rn(a7)};
    *(uint4*)(dst + (size_t)row * 256 + lane * 8) = *(uint4*)o;
}

// ---------------- weight prep ----------------
__global__ void prep_w_f16(const float* __restrict__ W1, const float* __restrict__ W2,
                           const float* __restrict__ W3, const float* __restrict__ W4,
                           __half* __restrict__ Bh, __half* __restrict__ W4p) {
    int n = blockIdx.x;
    int k = threadIdx.x;
    int l = blockIdx.y;
    if (l < 3) {
        const float* W = (l == 0) ? W1 : (l == 1) ? W2 : W3;
        Bh[(size_t)l * NF * NF + (size_t)n * NF + k] = __float2half_rn(W[(size_t)k * NF + n]);
    } else if (n < 64) {
        W4p[(size_t)n * NF + k] = (n < 40) ? __float2half_rn(W4[(size_t)k * 40 + n])
                                           : __ushort_as_half((unsigned short)0);
    }
}

// ---------------- shared tile layout ----------------
#define PITCH 72
#define A_SZ1 (128 * PITCH * 2)
#define B_SZ1 (256 * PITCH * 2)
#define STAGE1 (A_SZ1 + B_SZ1)
#define FUSED_SMEM (3 * STAGE1)
#define H1_PITCH 264
#define H1_OFF 0
#define B2_OFF0 68608
#define B2_OFF1 (68608 + 36864)
#define BIAS_OFF (B2_OFF1 + 36864)

// ---------------- fused GEMM1+GEMM2 ----------------
__global__ void __launch_bounds__(512) fused_mlp2_kernel(
    const __half* __restrict__ Ah, const __half* __restrict__ W1h,
    const float* __restrict__ b1, const __half* __restrict__ W2h,
    const float* __restrict__ b2, __half* __restrict__ Out, int M) {
    extern __shared__ char smem[];
    uint32_t sbase = smem_u32(smem);
    uint32_t sh1 = sbase + H1_OFF;

    int tid = threadIdx.x, lane = tid & 31, wid = tid >> 5;
    int m0 = blockIdx.x * 128;
    int wm = (wid >> 2) * 32;
    int wn = (wid & 3) * 64;

    int arow = tid >> 2, aq = tid & 3;
    int gmA = m0 + arow; if (gmA >= M) gmA = M - 1;
    int brow = tid >> 1, bh = tid & 1;

    float acc[2][8][4];
#pragma unroll
    for (int i = 0; i < 2; i++)
#pragma unroll
        for (int j = 0; j < 8; j++)
#pragma unroll
            for (int q = 0; q < 4; q++) acc[i][j][q] = 0.f;

    auto issue1 = [&](int it, int stg) {
        uint32_t sA = sbase + stg * STAGE1;
        uint32_t sB = sA + A_SZ1;
        const __half* asrc = Ah + (size_t)gmA * NF + it * 64 + aq * 16;
        uint32_t adst = sA + (uint32_t)(arow * PITCH + aq * 16) * 2;
        CP_ASYNC16(adst, asrc);
        CP_ASYNC16(adst + 16, asrc + 8);
        const __half* bsrc = W1h + (size_t)brow * NF + it * 64 + bh * 32;
        uint32_t bdst = sB + (uint32_t)(brow * PITCH + bh * 32) * 2;
#pragma unroll
        for (int j = 0; j < 4; j++) CP_ASYNC16(bdst + j * 16, bsrc + j * 8);
        CP_COMMIT();
    };

    auto compute1 = [&](int stg) {
        uint32_t sA = sbase + stg * STAGE1;
        uint32_t sB = sA + A_SZ1;
#pragma unroll
        for (int ks = 0; ks < 4; ks++) {
            uint32_t af[2][4];
#pragma unroll
            for (int mt = 0; mt < 2; mt++) {
                uint32_t addr = sA +
                    (uint32_t)((wm + mt * 16 + (lane & 15)) * PITCH + ks * 16 +
                               ((lane >> 4) << 3)) * 2;
                LDSM_X4(af[mt][0], af[mt][1], af[mt][2], af[mt][3], addr);
            }
            uint32_t bf[4][4];
#pragma unroll
            for (int p = 0; p < 4; p++) {
                uint32_t addr = sB +
                    (uint32_t)((wn + p * 16 + ((lane >> 4) << 3) + (lane & 7)) * PITCH +
                               ks * 16 + ((lane >> 3) & 1) * 8) * 2;
                LDSM_X4(bf[p][0], bf[p][1], bf[p][2], bf[p][3], addr);
            }
#pragma unroll
            for (int mt = 0; mt < 2; mt++)
#pragma unroll
                for (int nt = 0; nt < 8; nt++)
                    mma_f16(acc[mt][nt], af[mt], &bf[nt >> 1][(nt & 1) * 2]);
        }
    };

    issue1(0, 0);
    issue1(1, 1);
    for (int it = 0; it < 4; it++) {
        if (it < 3) CP_WAIT1(); else CP_WAIT0();
        __syncthreads();
        compute1(it % 3);
        if (it + 2 < 4) issue1(it + 2, (it + 2) % 3);
    }
    __syncthreads();

    // h1 = relu(acc + b1) -> smem; reset acc
#pragma unroll
    for (int mt = 0; mt < 2; mt++) {
        int r0 = wm + mt * 16 + (lane >> 2);
#pragma unroll
        for (int nt = 0; nt < 8; nt++) {
            int n = wn + nt * 8 + (lane & 3) * 2;
            float c0 = __ldg(b1 + n), c1 = __ldg(b1 + n + 1);
#pragma unroll
            for (int h = 0; h < 2; h++) {
                int r = r0 + h * 8;
                __half ph[2] = {
                    __float2half_rn(fmaxf(acc[mt][nt][h * 2 + 0] + c0, 0.f)),
                    __float2half_rn(fmaxf(acc[mt][nt][h * 2 + 1] + c1, 0.f))};
                asm volatile("st.shared.b32 [%0], %1;"
                             :: "r"(sh1 + (uint32_t)(r * H1_PITCH + n) * 2),
                                "r"(*(uint32_t*)ph));
                acc[mt][nt][h * 2 + 0] = 0.f;
                acc[mt][nt][h * 2 + 1] = 0.f;
            }
        }
    }
    __syncthreads();

    // phase 2: h1(smem) @ W2
    uint32_t sB2[2] = {sbase + B2_OFF0, sbase + B2_OFF1};

    auto issue2 = [&](int kc, int buf) {
        const __half* bsrc = W2h + (size_t)brow * NF + kc * 64 + bh * 32;
        uint32_t bdst = sB2[buf] + (uint32_t)(brow * PITCH + bh * 32) * 2;
#pragma unroll
        for (int j = 0; j < 4; j++) CP_ASYNC16(bdst + j * 16, bsrc + j * 8);
        CP_COMMIT();
    };

    auto compute2 = [&](int kc, int buf) {
        uint32_t sB = sB2[buf];
#pragma unroll
        for (int ks = 0; ks < 4; ks++) {
            uint32_t af[2][4];
#pragma unroll
            for (int mt = 0; mt < 2; mt++) {
                uint32_t addr = sh1 +
                    (uint32_t)((wm + mt * 16 + (lane & 15)) * H1_PITCH + kc * 64 +
                               ks * 16 + ((lane >> 4) << 3)) * 2;
                LDSM_X4(af[mt][0], af[mt][1], af[mt][2], af[mt][3], addr);
            }
            uint32_t bf[4][4];
#pragma unroll
            for (int p = 0; p < 4; p++) {
                uint32_t addr = sB +
                    (uint32_t)((wn + p * 16 + ((lane >> 4) << 3) + (lane & 7)) * PITCH +
                               ks * 16 + ((lane >> 3) & 1) * 8) * 2;
                LDSM_X4(bf[p][0], bf[p][1], bf[p][2], bf[p][3], addr);
            }
#pragma unroll
            for (int mt = 0; mt < 2; mt++)
#pragma unroll
                for (int nt = 0; nt < 8; nt++)
                    mma_f16(acc[mt][nt], af[mt], &bf[nt >> 1][(nt & 1) * 2]);
        }
    };

    issue2(0, 0);
    issue2(1, 1);
    for (int kc = 0; kc < 4; kc++) {
        if (kc < 3) CP_WAIT1(); else CP_WAIT0();
        __syncthreads();
        compute2(kc, kc & 1);
        if (kc + 2 < 4) {
            __syncthreads();
            issue2(kc + 2, kc & 1);
        }
    }

    // epilogue: h2 -> gmem fp16
#pragma unroll
    for (int mt = 0; mt < 2; mt++) {
        int rr[2];
        rr[0] = m0 + wm + mt * 16 + (lane >> 2);
        rr[1] = rr[0] + 8;
#pragma unroll
        for (int nt = 0; nt < 8; nt++) {
            int n = wn + nt * 8 + (lane & 3) * 2;
            float c0 = __ldg(b2 + n), c1 = __ldg(b2 + n + 1);
#pragma unroll
            for (int h = 0; h < 2; h++) {
                int r = rr[h];
                if (r >= M) continue;
                __half ph[2] = {
                    __float2half_rn(fmaxf(acc[mt][nt][h * 2 + 0] + c0, 0.f)),
                    __float2half_rn(fmaxf(acc[mt][nt][h * 2 + 1] + c1, 0.f))};
                *(uint32_t*)(Out + (size_t)r * NF + n) = *(uint32_t*)ph;
            }
        }
    }
}

// ---------------- fused GEMM3 + final GEMM(40) + log_softmax ----------------
__global__ void __launch_bounds__(512) fused_out_kernel(
    const __half* __restrict__ Ah, const __half* __restrict__ W3h,
    const float* __restrict__ b3, const __half* __restrict__ W4p,
    const float* __restrict__ b4, float* __restrict__ Out, int M) {
    extern __shared__ char smem[];
    uint32_t sbase = smem_u32(smem);
    uint32_t sh1 = sbase + H1_OFF;

    int tid = threadIdx.x, lane = tid & 31, wid = tid >> 5;
    int m0 = blockIdx.x * 128;
    int wm = (wid >> 2) * 32;
    int wn = (wid & 3) * 64;

    int arow = tid >> 2, aq = tid & 3;
    int gmA = m0 + arow; if (gmA >= M) gmA = M - 1;
    int brow = tid >> 1, bh = tid & 1;

    float* sbias = (float*)(smem + BIAS_OFF);   // written AFTER phase 1

    float acc[2][8][4];
#pragma unroll
    for (int i = 0; i < 2; i++)
#pragma unroll
        for (int j = 0; j < 8; j++)
#pragma unroll
            for (int q = 0; q < 4; q++) acc[i][j][q] = 0.f;

    auto issue1 = [&](int it, int stg) {
        uint32_t sA = sbase + stg * STAGE1;
        uint32_t sB = sA + A_SZ1;
        const __half* asrc = Ah + (size_t)gmA * NF + it * 64 + aq * 16;
        uint32_t adst = sA + (uint32_t)(arow * PITCH + aq * 16) * 2;
        CP_ASYNC16(adst, asrc);
        CP_ASYNC16(adst + 16, asrc + 8);
        const __half* bsrc = W3h + (size_t)brow * NF + it * 64 + bh * 32;
        uint32_t bdst = sB + (uint32_t)(brow * PITCH + bh * 32) * 2;
#pragma unroll
        for (int j = 0; j < 4; j++) CP_ASYNC16(bdst + j * 16, bsrc + j * 8);
        CP_COMMIT();
    };

    auto compute1 = [&](int stg) {
        uint32_t sA = sbase + stg * STAGE1;
        uint32_t sB = sA + A_SZ1;
#pragma unroll
        for (int ks = 0; ks < 4; ks++) {
            uint32_t af[2][4];
#pragma unroll
            for (int mt = 0; mt < 2; mt++) {
                uint32_t addr = sA +
                    (uint32_t)((wm + mt * 16 + (lane & 15)) * PITCH + ks * 16 +
                               ((lane >> 4) << 3)) * 2;
                LDSM_X4(af[mt][0], af[mt][1], af[mt][2], af[mt][3], addr);
            }
            uint32_t bf[4][4];
#pragma unroll
            for (int p = 0; p < 4; p++) {
                uint32_t addr = sB +
                    (uint32_t)((wn + p * 16 + ((lane >> 4) << 3) + (lane & 7)) * PITCH +
                               ks * 16 + ((lane >> 3) & 1) * 8) * 2;
                LDSM_X4(bf[p][0], bf[p][1], bf[p][2], bf[p][3], addr);
            }
#pragma unroll
            for (int mt = 0; mt < 2; mt++)
#pragma unroll
                for (int nt = 0; nt < 8; nt++)
                    mma_f16(acc[mt][nt], af[mt], &bf[nt >> 1][(nt & 1) * 2]);
        }
    };

    issue1(0, 0);
    issue1(1, 1);
    for (int it = 0; it < 4; it++) {
        if (it < 3) CP_WAIT1(); else CP_WAIT0();
        __syncthreads();
        compute1(it % 3);
        if (it + 2 < 4) issue1(it + 2, (it + 2) % 3);
    }
    __syncthreads();

    if (tid < 64) sbias[tid] = (tid < 40) ? b4[tid] : -1e30f;
#pragma unroll
    for (int mt = 0; mt < 2; mt++) {
        int r0 = wm + mt * 16 + (lane >> 2);
#pragma unroll
        for (int nt = 0; nt < 8; nt++) {
            int n = wn + nt * 8 + (lane & 3) * 2;
            float c0 = __ldg(b3 + n), c1 = __ldg(b3 + n + 1);
#pragma unroll
            for (int h = 0; h < 2; h++) {
                int r = r0 + h * 8;
                __half ph[2] = {
                    __float2half_rn(fmaxf(acc[mt][nt][h * 2 + 0] + c0, 0.f)),
                    __float2half_rn(fmaxf(acc[mt][nt][h * 2 + 1] + c1, 0.f))};
                asm volatile("st.shared.b32 [%0], %1;"
                             :: "r"(sh1 + (uint32_t)(r * H1_PITCH + n) * 2),
                                "r"(*(uint32_t*)ph));
            }
        }
    }

    uint32_t sW4 = sbase + B2_OFF0;
    if (tid < 128) {
        int br = tid >> 1, bq = tid & 1;
#pragma unroll
        for (int kc = 0; kc < 4; kc++) {
            const __half* bsrc = W4p + (size_t)br * NF + kc * 64 + bq * 32;
            uint32_t bdst = sW4 + (uint32_t)(kc * 64 * PITCH + br * PITCH + bq * 32) * 2;
#pragma unroll
            for (int j = 0; j < 4; j++) CP_ASYNC16(bdst + j * 16, bsrc + j * 8);
        }
    }
    CP_COMMIT();
    CP_WAIT0();
    __syncthreads();

    if (wid < 8) {
        float acc2[8][4];
#pragma unroll
        for (int j = 0; j < 8; j++)
#pragma unroll
            for (int q = 0; q < 4; q++) acc2[j][q] = 0.f;

#pragma unroll
        for (int kc = 0; kc < 4; kc++) {
#pragma unroll
            for (int ks = 0; ks < 4; ks++) {
                uint32_t af[4];
                uint32_t aaddr = sh1 +
                    (uint32_t)((wid * 16 + (lane & 15)) * H1_PITCH + kc * 64 +
                               ks * 16 + ((lane >> 4) << 3)) * 2;
                LDSM_X4(af[0], af[1], af[2], af[3], aaddr);
                uint32_t bf[4][4];
#pragma unroll
                for (int p = 0; p < 4; p++) {
                    uint32_t baddr = sW4 +
                        (uint32_t)(kc * 64 * PITCH +
                                   (p * 16 + ((lane >> 4) << 3) + (lane & 7)) * PITCH +
                                   ks * 16 + ((lane >> 3) & 1) * 8) * 2;
                    LDSM_X4(bf[p][0], bf[p][1], bf[p][2], bf[p][3], baddr);
                }
#pragma unroll
                for (int nt = 0; nt < 8; nt++)
                    mma_f16(acc2[nt], af, &bf[nt >> 1][(nt & 1) * 2]);
            }
        }

#pragma unroll
        for (int h = 0; h < 2; h++) {
            int gr = m0 + wid * 16 + (lane >> 2) + h * 8;
            float lg[16];
            float mx = -1e30f;
#pragma unroll
            for (int nt = 0; nt < 8; nt++) {
                int c = nt * 8 + (lane & 3) * 2;
                lg[nt * 2 + 0] = acc2[nt][h * 2 + 0] + sbias[c];
                lg[nt * 2 + 1] = acc2[nt][h * 2 + 1] + sbias[c + 1];
                mx = fmaxf(mx, fmaxf(lg[nt * 2], lg[nt * 2 + 1]));
            }
            mx = fmaxf(mx, __shfl_xor_sync(0xffffffffu, mx, 1));
            mx = fmaxf(mx, __shfl_xor_sync(0xffffffffu, mx, 2));
            float s = 0.f;
#pragma unroll
            for (int q = 0; q < 16; q++) s += __expf(lg[q] - mx);
            s += __shfl_xor_sync(0xffffffffu, s, 1);
            s += __shfl_xor_sync(0xffffffffu, s, 2);
            float lse = mx + __logf(s);
            if (gr < M) {
#pragma unroll
                for (int nt = 0; nt < 5; nt++) {
                    int c = nt * 8 + (lane & 3) * 2;
                    if (c < 40) {
                        float2 o;
                        o.x = lg[nt * 2 + 0] - lse;
                        o.y = lg[nt * 2 + 1] - lse;
                        *(float2*)(Out + (size_t)gr * 40 + c) = o;
                    }
                }
            }
        }
    }
}

// ---------------- launch ----------------
extern "C" void kernel_launch(void* const* d_in, const int* in_sizes, int n_in,
                              void* d_out, int out_size) {
    const float* x    = (const float*)d_in[0];
    const int*   erow = (const int*)d_in[1];
    const int*   ecol = (const int*)d_in[2];
    const float* ew   = (const float*)d_in[3];
    const float* W1 = (const float*)d_in[4];
    const float* b1 = (const float*)d_in[5];
    const float* W2 = (const float*)d_in[6];
    const float* b2 = (const float*)d_in[7];
    const float* W3 = (const float*)d_in[8];
    const float* b3 = (const float*)d_in[9];
    const float* W4 = (const float*)d_in[10];
    const float* b4 = (const float*)d_in[11];
    float* out = (float*)d_out;

    int E = in_sizes[1];
    int n = in_sizes[0] / NF;

    __half *wh, *h0, *h1, *h2, *w4p;
    int* rowptr;
    cudaGetSymbolAddress((void**)&rowptr, g_rowptr);
    cudaGetSymbolAddress((void**)&wh, g_Wh);
    cudaGetSymbolAddress((void**)&h0, g_h0);
    cudaGetSymbolAddress((void**)&h1, g_h1);
    cudaGetSymbolAddress((void**)&h2, g_h2);
    cudaGetSymbolAddress((void**)&w4p, g_W4p);

    static bool inited = false;
    static cudaStream_t sB;
    static cudaEvent_t ev0, evS1[NCHUNK], evJ1, evS2[NCHUNK], evJ2;
    if (!inited) {
        cudaStreamCreateWithFlags(&sB, cudaStreamNonBlocking);
        cudaEventCreateWithFlags(&ev0, cudaEventDisableTiming);
        cudaEventCreateWithFlags(&evJ1, cudaEventDisableTiming);
        cudaEventCreateWithFlags(&evJ2, cudaEventDisableTiming);
        for (int c = 0; c < NCHUNK; c++) {
            cudaEventCreateWithFlags(&evS1[c], cudaEventDisableTiming);
            cudaEventCreateWithFlags(&evS2[c], cudaEventDisableTiming);
        }
        cudaFuncSetAttribute(fused_mlp2_kernel,
                             cudaFuncAttributeMaxDynamicSharedMemorySize, FUSED_SMEM);
        cudaFuncSetAttribute(fused_out_kernel,
                             cudaFuncAttributeMaxDynamicSharedMemorySize, FUSED_SMEM);
        inited = true;
    }

    int total4 = n * 64;
    int chN = (total4 > E) ? total4 : E;

    // ---- default stream: CSR build + x conv (x -> h0) ----
    cudaMemsetAsync(rowptr, 0, (size_t)(n + 1) * sizeof(int));
    conv_hist_kernel<<<(chN / 2 + 255) / 256, 256>>>(x, h0, erow, E, total4);
    scan_kernel<<<1, 1024>>>(n);
    scatter_kernel<<<(E / 4 + 255) / 256, 256>>>(erow, ecol, ew, E);
    cudaEventRecord(ev0, 0);

    // ---- side stream: weight prep ----
    cudaStreamWaitEvent(sB, ev0, 0);
    dim3 pgrid(256, 4);
    prep_w_f16<<<pgrid, 256, 0, sB>>>(W1, W2, W3, W4, wh, w4p);

    // row chunks
    int r0s[NCHUNK], cnts[NCHUNK];
    for (int c = 0; c < NCHUNK; c++) {
        int r0 = c * CHUNK_ROWS;
        int cnt = n - r0;
        if (cnt > CHUNK_ROWS) cnt = CHUNK_ROWS;
        if (cnt < 0) cnt = 0;
        r0s[c] = r0;
        cnts[c] = cnt;
    }

    // ---- boundary 1: spmm1 h0->h1 (default), mlp2 h1->h2 (sB) — disjoint buffers ----
    for (int c = 0; c < NCHUNK; c++) {
        if (cnts[c] == 0) continue;
        spmm_f16_kernel<<<(cnts[c] * 32 + 255) / 256, 256>>>(h0, h1, r0s[c],
                                                             r0s[c] + cnts[c]);
        cudaEventRecord(evS1[c], 0);
        cudaStreamWaitEvent(sB, evS1[c], 0);
        fused_mlp2_kernel<<<(cnts[c] + 127) / 128, 512, FUSED_SMEM, sB>>>(
            h1 + (size_t)r0s[c] * NF, wh + 0 * (size_t)NF * NF, b1,
            wh + 1 * (size_t)NF * NF, b2, h2 + (size_t)r0s[c] * NF, cnts[c]);
    }
    cudaEventRecord(evJ1, sB);
    cudaStreamWaitEvent(0, evJ1, 0);

    // ---- boundary 2: spmm2 h2->h1 (default), fused_out h1->out (sB) ----
    for (int c = 0; c < NCHUNK; c++) {
        if (cnts[c] == 0) continue;
        spmm_f16_kernel<<<(cnts[c] * 32 + 255) / 256, 256>>>(h2, h1, r0s[c],
                                                             r0s[c] + cnts[c]);
        cudaEventRecord(evS2[c], 0);
        cudaStreamWaitEvent(sB, evS2[c], 0);
        fused_out_kernel<<<(cnts[c] + 127) / 128, 512, FUSED_SMEM, sB>>>(
            h1 + (size_t)r0s[c] * NF, wh + 2 * (size_t)NF * NF, b3, w4p, b4,
            out + (size_t)r0s[c] * 40, cnts[c]);
    }
    cudaEventRecord(evJ2, sB);
    cudaStreamWaitEvent(0, evJ2, 0);
}